// round 3
// baseline (speedup 1.0000x reference)
#include <cuda_runtime.h>
#include <math.h>

#define NPTS 32768
#define NB 16
#define WSTRIDE 4560   // per-batch hyper weights: 30*62 + 3*30*30

typedef unsigned long long u64;

// ---------------- scratch (device globals; no allocations allowed) ----------
__device__ float g_W[NB * WSTRIDE];          // normalized hyper weights
__device__ float g_enc[NPTS * 64];           // nerf encoding, padded to 64
__device__ float g_g[NB * NPTS * 30];        // output of hyper layers (63MB)

// ---------------- packed f32x2 helpers (Blackwell) ---------------------------
__device__ __forceinline__ u64 pk2(float lo, float hi) {
    u64 r; asm("mov.b64 %0,{%1,%2};" : "=l"(r) : "f"(lo), "f"(hi)); return r;
}
__device__ __forceinline__ float2 up2(u64 v) {
    float2 r; asm("mov.b64 {%0,%1},%2;" : "=f"(r.x), "=f"(r.y) : "l"(v)); return r;
}
__device__ __forceinline__ u64 fma2(u64 a, u64 b, u64 c) {
    u64 r; asm("fma.rn.f32x2 %0,%1,%2,%3;" : "=l"(r) : "l"(a), "l"(b), "l"(c));
    return r;
}

// ---------------- misc helpers ----------------------------------------------
__device__ __forceinline__ float silu_f(float z) {
    float e = __expf(-z);
    return __fdividef(z, 1.0f + e);
}

// Accurate sin regardless of -use_fast_math: double Cody-Waite + f32 poly.
__device__ __forceinline__ float sin_accurate(float xf) {
    double x = (double)xf;
    double kd = rint(x * 0.63661977236758138);
    long long ki = (long long)kd;
    double r = fma(kd, -1.5707963267948966, x);
    r = fma(kd, -6.123233995736766e-17, r);
    float rf = (float)r;
    float s2 = rf * rf;
    float ps = fmaf(s2, 2.7525562e-6f, -1.9840874e-4f);
    ps = fmaf(s2, ps, 8.3333310e-3f);
    ps = fmaf(s2, ps, -1.6666667e-1f);
    float sinv = fmaf(rf * s2, ps, rf);
    float pc = fmaf(s2, 2.4433157e-5f, -1.3888378e-3f);
    pc = fmaf(s2, pc, 4.1666638e-2f);
    pc = fmaf(s2, pc, -0.5f);
    float cosv = fmaf(s2, pc, 1.0f);
    int q = (int)(ki & 3);
    float res = (q & 1) ? cosv : sinv;
    if (q & 2) res = -res;
    return res;
}

// ---------------- K0: nerf encoding -----------------------------------------
__global__ __launch_bounds__(256) void enc_kernel(const float* __restrict__ x) {
    int p = blockIdx.x * 256 + threadIdx.x;
    float x0 = x[2 * p], x1 = x[2 * p + 1];
    float* o = g_enc + p * 64;
    const float HPI = 1.5707963267948966f;
    o[0] = x0; o[1] = x1;
#pragma unroll
    for (int s = 0; s < 15; ++s) {
        float sc = (float)(1 << s);
        float a0 = x0 * sc, a1 = x1 * sc;
        o[2 + 2 * s]  = sin_accurate(a0);
        o[3 + 2 * s]  = sin_accurate(a1);
        o[32 + 2 * s] = sin_accurate(a0 + HPI);
        o[33 + 2 * s] = sin_accurate(a1 + HPI);
    }
    o[62] = 0.0f; o[63] = 0.0f;
}

// ---------------- K1: fused hyper weight generation (all 4 layers) ----------
struct HP {
    const float* pw[4];
    const float* pb[4];
    const float* lnw[4];
    const float* lnb[4];
};

__global__ __launch_bounds__(256) void hyperw_kernel(const float* __restrict__ sdf, HP hp) {
    __shared__ float wbuf[30 * 62];
    int b  = blockIdx.x & 15;
    int li = blockIdx.x >> 4;
    int c    = (li == 0) ? 62 : 30;
    int woff = (li == 0) ? 0  : 1860 + (li - 1) * 900;
    const float* pw  = hp.pw[li];
    const float* pb  = hp.pb[li];
    const float* lnw = hp.lnw[li];
    const float* lnb = hp.lnb[li];

    int tid = threadIdx.x;
    int tot = 30 * c;
    for (int e = tid; e < tot; e += 256) {
        int v = e / c, cc = e - v * c;
        const float4* sl4 = (const float4*)(sdf + ((b * 120) + li * 30 + v) * 120);
        const float4* pw4 = (const float4*)(pw + (v * c + cc) * 120);
        float acc = 0.0f;
#pragma unroll
        for (int d = 0; d < 30; ++d) {
            float4 a = sl4[d], w = pw4[d];
            acc = fmaf(a.x, w.x, acc); acc = fmaf(a.y, w.y, acc);
            acc = fmaf(a.z, w.z, acc); acc = fmaf(a.w, w.w, acc);
        }
        wbuf[e] = acc + pb[e];
    }
    __syncthreads();
    if (tid < 30) {
        int v = tid;
        const float* row = wbuf + v * c;
        float mu = 0.0f;
        for (int cc = 0; cc < c; ++cc) mu += row[cc];
        mu /= (float)c;
        float var = 0.0f;
        for (int cc = 0; cc < c; ++cc) { float d = row[cc] - mu; var = fmaf(d, d, var); }
        var /= (float)c;
        float inv = rsqrtf(var + 1e-5f);
        float* dst = g_W + b * WSTRIDE + woff + v * c;
        for (int cc = 0; cc < c; ++cc)
            dst[cc] = (row[cc] - mu) * inv * lnw[cc] + lnb[cc];
    }
}

// ---------------- K2: apply 4 hyper layers (f32x2 packed) --------------------
__global__ __launch_bounds__(256) void hyper_apply_kernel(
    const float* __restrict__ b0, const float* __restrict__ b1,
    const float* __restrict__ b2, const float* __restrict__ b3) {
    __shared__ float sW[WSTRIDE];
    __shared__ float sb[120];
    int b = blockIdx.y;
    int tid = threadIdx.x;
    const float* Wb = g_W + b * WSTRIDE;
    for (int i = tid; i < WSTRIDE; i += 256) sW[i] = Wb[i];
    if (tid < 30) sb[tid] = b0[tid];
    else if (tid < 60) sb[tid] = b1[tid - 30];
    else if (tid < 90) sb[tid] = b2[tid - 60];
    else if (tid < 120) sb[tid] = b3[tid - 90];
    __syncthreads();

    int p = blockIdx.x * 256 + tid;
    // h pairs packed: 31 x f32x2
    u64 hpr[31];
    const u64* e8 = (const u64*)(g_enc + p * 64);
#pragma unroll
    for (int i = 0; i < 31; ++i) hpr[i] = e8[i];

    float a[30];
    // layer 0: 62 -> 30
#pragma unroll
    for (int oo = 0; oo < 30; ++oo) {
        const u64* w8 = (const u64*)(sW + oo * 62);
        u64 acc = 0ull;
#pragma unroll
        for (int i = 0; i < 31; ++i) acc = fma2(hpr[i], w8[i], acc);
        float2 f = up2(acc);
        a[oo] = silu_f(f.x + f.y + sb[oo]);
    }
    // layers 1..3: 30 -> 30
#pragma unroll
    for (int l = 1; l <= 3; ++l) {
        int off = 1860 + (l - 1) * 900;
        u64 ap[15];
#pragma unroll
        for (int i = 0; i < 15; ++i) ap[i] = pk2(a[2 * i], a[2 * i + 1]);
        float t[30];
#pragma unroll
        for (int oo = 0; oo < 30; ++oo) {
            const u64* w8 = (const u64*)(sW + off + oo * 30);
            u64 acc = 0ull;
#pragma unroll
            for (int i = 0; i < 15; ++i) acc = fma2(ap[i], w8[i], acc);
            float2 f = up2(acc);
            t[oo] = silu_f(f.x + f.y + sb[l * 30 + oo]);
        }
#pragma unroll
        for (int oo = 0; oo < 30; ++oo) a[oo] = t[oo];
    }
    u64* gout = (u64*)(g_g + (b * NPTS + p) * 30);
#pragma unroll
    for (int i = 0; i < 15; ++i) gout[i] = pk2(a[2 * i], a[2 * i + 1]);
}

// ---------------- K3: fused MLP 30->256->128->1 (f32x2) ----------------------
// Warp = 8 points x 4 q-lanes. Lane (q,pp): phase1 owns h1[q*64..q*64+63] of
// point pp; phase2 owns h2 j in [q*32, q*32+32) of point pp as 16 f32x2 pairs.
// W1 stored transposed [k][j] pitch 128 with per-quarter chunk swizzle
// (chunk slot = (c+q)&7) -> the four q-lane 16B chunks hit disjoint bank quads.
#define K3_SW0_SZ (256 * 32 + 16)
#define K3_SMEM_FLOATS (K3_SW0_SZ + 256 + 256 * 128 + 128 + 128)
#define K3_SMEM_BYTES (K3_SMEM_FLOATS * 4)

__global__ __launch_bounds__(256, 1) void mlp_kernel(
    const float* __restrict__ w0, const float* __restrict__ b0,
    const float* __restrict__ w1, const float* __restrict__ b1,
    const float* __restrict__ w2, const float* __restrict__ b2v,
    float* __restrict__ out) {
    extern __shared__ float sm[];
    float* sW0  = sm;                      // swizzled rows: k*32 + (k>>6)*4
    float* sB0  = sW0 + K3_SW0_SZ;
    float* sW1T = sB0 + 256;               // [k][j] pitch 128, chunk-swizzled
    float* sB1  = sW1T + 256 * 128;
    float* sW2  = sB1 + 128;

    int tid = threadIdx.x;
    {
        int k = tid;
#pragma unroll
        for (int i = 0; i < 30; ++i)
            sW0[k * 32 + (k >> 6) * 4 + i] = w0[k * 30 + i];
        sW0[k * 32 + (k >> 6) * 4 + 30] = 0.0f;
        sW0[k * 32 + (k >> 6) * 4 + 31] = 0.0f;
        sB0[tid] = b0[tid];
        if (tid < 128) { sB1[tid] = b1[tid]; sW2[tid] = w2[tid]; }
    }
    for (int idx = tid; idx < 128 * 256; idx += 256) {
        int j = idx >> 8, k = idx & 255;     // w1[idx] coalesced
        int qj = j >> 5, cj = (j >> 2) & 7, ej = j & 3;
        sW1T[k * 128 + qj * 32 + ((cj + qj) & 7) * 4 + ej] = w1[idx];
    }
    float bias2 = __ldg(b2v);
    __syncthreads();

    int lane = tid & 31, warp = tid >> 5;
    int q = lane & 3, pp = lane >> 2;
    int grp = warp * 8 + pp;
    int b = blockIdx.y;

#pragma unroll 1
    for (int it = 0; it < 4; ++it) {
        int p = blockIdx.x * 256 + it * 64 + grp;
        // g pairs for this point (15 x f32x2), 8B-aligned (30 floats/row)
        u64 gp[15];
        const u64* g8 = (const u64*)(g_g + (b * NPTS + p) * 30);
#pragma unroll
        for (int i = 0; i < 15; ++i) gp[i] = g8[i];

        // phase 1: 64 h1 values for this lane's q-quarter
        float s[64];
        const float* w0row0 = sW0 + q * 64 * 32 + q * 4;
#pragma unroll
        for (int m = 0; m < 64; ++m) {
            const ulonglong2* wr = (const ulonglong2*)(w0row0 + m * 32);
            u64 acc = 0ull;
#pragma unroll
            for (int i4 = 0; i4 < 7; ++i4) {
                ulonglong2 wv = wr[i4];
                acc = fma2(gp[2 * i4], wv.x, acc);
                acc = fma2(gp[2 * i4 + 1], wv.y, acc);
            }
            acc = fma2(gp[14], *(const u64*)((const float*)wr + 28), acc);
            float2 f = up2(acc);
            s[m] = silu_f(f.x + f.y + sB0[q * 64 + m]);
        }

        // phase 2: h2 j-pairs, accumulate over all 256 k via shfl broadcast
        u64 acc2[16];
#pragma unroll
        for (int c = 0; c < 8; ++c) {
            acc2[2 * c]     = *(const u64*)(sB1 + q * 32 + c * 4);
            acc2[2 * c + 1] = *(const u64*)(sB1 + q * 32 + c * 4 + 2);
        }

#pragma unroll 1
        for (int qs = 0; qs < 4; ++qs) {
            int srcl = (pp << 2) | qs;
            const float* wkbase = sW1T + (qs * 64) * 128 + q * 32;
#pragma unroll
            for (int m = 0; m < 64; ++m) {
                float sk = __shfl_sync(0xffffffffu, s[m], srcl);
                u64 skk = pk2(sk, sk);
                const float* wrow = wkbase + m * 128;
#pragma unroll
                for (int c = 0; c < 8; ++c) {
                    ulonglong2 wv = *(const ulonglong2*)(wrow + ((c + q) & 7) * 4);
                    acc2[2 * c]     = fma2(wv.x, skk, acc2[2 * c]);
                    acc2[2 * c + 1] = fma2(wv.y, skk, acc2[2 * c + 1]);
                }
            }
        }

        // epilogue: out = sum_j w2[j]*silu(h2[j]) + b2, reduce 4 q-lanes
        float r = 0.0f;
#pragma unroll
        for (int c = 0; c < 8; ++c) {
#pragma unroll
            for (int t = 0; t < 2; ++t) {
                float2 h2 = up2(acc2[2 * c + t]);
                int j = q * 32 + c * 4 + 2 * t;
                r = fmaf(sW2[j],     silu_f(h2.x), r);
                r = fmaf(sW2[j + 1], silu_f(h2.y), r);
            }
        }
        r += __shfl_xor_sync(0xffffffffu, r, 1);
        r += __shfl_xor_sync(0xffffffffu, r, 2);
        if (q == 0) out[b * NPTS + p] = r + bias2;
    }
}

// ---------------- launch -----------------------------------------------------
extern "C" void kernel_launch(void* const* d_in, const int* in_sizes, int n_in,
                              void* d_out, int out_size) {
    const float* x   = (const float*)d_in[0];
    const float* sdf = (const float*)d_in[1];
    HP hp;
    hp.pw[0]  = (const float*)d_in[2];  hp.pw[1]  = (const float*)d_in[7];
    hp.pw[2]  = (const float*)d_in[12]; hp.pw[3]  = (const float*)d_in[17];
    hp.pb[0]  = (const float*)d_in[3];  hp.pb[1]  = (const float*)d_in[8];
    hp.pb[2]  = (const float*)d_in[13]; hp.pb[3]  = (const float*)d_in[18];
    hp.lnw[0] = (const float*)d_in[4];  hp.lnw[1] = (const float*)d_in[9];
    hp.lnw[2] = (const float*)d_in[14]; hp.lnw[3] = (const float*)d_in[19];
    hp.lnb[0] = (const float*)d_in[5];  hp.lnb[1] = (const float*)d_in[10];
    hp.lnb[2] = (const float*)d_in[15]; hp.lnb[3] = (const float*)d_in[20];
    const float* bias[4] = {(const float*)d_in[6],  (const float*)d_in[11],
                            (const float*)d_in[16], (const float*)d_in[21]};
    const float* mw0 = (const float*)d_in[22];
    const float* mb0 = (const float*)d_in[23];
    const float* mw1 = (const float*)d_in[24];
    const float* mb1 = (const float*)d_in[25];
    const float* mw2 = (const float*)d_in[26];
    const float* mb2 = (const float*)d_in[27];
    float* out = (float*)d_out;

    cudaFuncSetAttribute(mlp_kernel, cudaFuncAttributeMaxDynamicSharedMemorySize,
                         K3_SMEM_BYTES);

    enc_kernel<<<NPTS / 256, 256>>>(x);
    hyperw_kernel<<<NB * 4, 256>>>(sdf, hp);

    dim3 g2(NPTS / 256, NB);
    hyper_apply_kernel<<<g2, 256>>>(bias[0], bias[1], bias[2], bias[3]);

    dim3 g3(NPTS / 256, NB);
    mlp_kernel<<<g3, 256, K3_SMEM_BYTES>>>(mw0, mb0, mw1, mb1, mw2, mb2, out);
}

// round 4
// speedup vs baseline: 1.9272x; 1.9272x over previous
#include <cuda_runtime.h>
#include <math.h>

#define NPTS 32768
#define NB 16
#define WSTRIDE 4560   // per-batch hyper weights: 30*62 + 3*30*30

typedef unsigned long long u64;

// ---------------- scratch (device globals; no allocations allowed) ----------
__device__ float g_W[NB * WSTRIDE];          // normalized hyper weights
__device__ float g_enc[NPTS * 64];           // nerf encoding, padded to 64
__device__ float g_g[NB * NPTS * 30];        // output of hyper layers (63MB)

// ---------------- packed f32x2 helpers (Blackwell) ---------------------------
__device__ __forceinline__ u64 pk2(float lo, float hi) {
    u64 r; asm("mov.b64 %0,{%1,%2};" : "=l"(r) : "f"(lo), "f"(hi)); return r;
}
__device__ __forceinline__ float2 up2(u64 v) {
    float2 r; asm("mov.b64 {%0,%1},%2;" : "=f"(r.x), "=f"(r.y) : "l"(v)); return r;
}
__device__ __forceinline__ u64 fma2(u64 a, u64 b, u64 c) {
    u64 r; asm("fma.rn.f32x2 %0,%1,%2,%3;" : "=l"(r) : "l"(a), "l"(b), "l"(c));
    return r;
}

// ---------------- misc helpers ----------------------------------------------
__device__ __forceinline__ float silu_f(float z) {
    float e = __expf(-z);
    return __fdividef(z, 1.0f + e);
}

// Accurate sin regardless of -use_fast_math: double Cody-Waite + f32 poly.
__device__ __forceinline__ float sin_accurate(float xf) {
    double x = (double)xf;
    double kd = rint(x * 0.63661977236758138);
    long long ki = (long long)kd;
    double r = fma(kd, -1.5707963267948966, x);
    r = fma(kd, -6.123233995736766e-17, r);
    float rf = (float)r;
    float s2 = rf * rf;
    float ps = fmaf(s2, 2.7525562e-6f, -1.9840874e-4f);
    ps = fmaf(s2, ps, 8.3333310e-3f);
    ps = fmaf(s2, ps, -1.6666667e-1f);
    float sinv = fmaf(rf * s2, ps, rf);
    float pc = fmaf(s2, 2.4433157e-5f, -1.3888378e-3f);
    pc = fmaf(s2, pc, 4.1666638e-2f);
    pc = fmaf(s2, pc, -0.5f);
    float cosv = fmaf(s2, pc, 1.0f);
    int q = (int)(ki & 3);
    float res = (q & 1) ? cosv : sinv;
    if (q & 2) res = -res;
    return res;
}

// ---------------- K0: nerf encoding -----------------------------------------
__global__ __launch_bounds__(256) void enc_kernel(const float* __restrict__ x) {
    int p = blockIdx.x * 256 + threadIdx.x;
    float x0 = x[2 * p], x1 = x[2 * p + 1];
    float* o = g_enc + p * 64;
    const float HPI = 1.5707963267948966f;
    o[0] = x0; o[1] = x1;
#pragma unroll
    for (int s = 0; s < 15; ++s) {
        float sc = (float)(1 << s);
        float a0 = x0 * sc, a1 = x1 * sc;
        o[2 + 2 * s]  = sin_accurate(a0);
        o[3 + 2 * s]  = sin_accurate(a1);
        o[32 + 2 * s] = sin_accurate(a0 + HPI);
        o[33 + 2 * s] = sin_accurate(a1 + HPI);
    }
    o[62] = 0.0f; o[63] = 0.0f;
}

// ---------------- K1: fused hyper weight generation (all 4 layers) ----------
struct HP {
    const float* pw[4];
    const float* pb[4];
    const float* lnw[4];
    const float* lnb[4];
};

__global__ __launch_bounds__(256) void hyperw_kernel(const float* __restrict__ sdf, HP hp) {
    __shared__ float wbuf[30 * 62];
    int b  = blockIdx.x & 15;
    int li = blockIdx.x >> 4;
    int c    = (li == 0) ? 62 : 30;
    int woff = (li == 0) ? 0  : 1860 + (li - 1) * 900;
    const float* pw  = hp.pw[li];
    const float* pb  = hp.pb[li];
    const float* lnw = hp.lnw[li];
    const float* lnb = hp.lnb[li];

    int tid = threadIdx.x;
    int tot = 30 * c;
    for (int e = tid; e < tot; e += 256) {
        int v = e / c, cc = e - v * c;
        const float4* sl4 = (const float4*)(sdf + ((b * 120) + li * 30 + v) * 120);
        const float4* pw4 = (const float4*)(pw + (v * c + cc) * 120);
        float acc = 0.0f;
#pragma unroll
        for (int d = 0; d < 30; ++d) {
            float4 a = sl4[d], w = pw4[d];
            acc = fmaf(a.x, w.x, acc); acc = fmaf(a.y, w.y, acc);
            acc = fmaf(a.z, w.z, acc); acc = fmaf(a.w, w.w, acc);
        }
        wbuf[e] = acc + pb[e];
    }
    __syncthreads();
    if (tid < 30) {
        int v = tid;
        const float* row = wbuf + v * c;
        float mu = 0.0f;
        for (int cc = 0; cc < c; ++cc) mu += row[cc];
        mu /= (float)c;
        float var = 0.0f;
        for (int cc = 0; cc < c; ++cc) { float d = row[cc] - mu; var = fmaf(d, d, var); }
        var /= (float)c;
        float inv = rsqrtf(var + 1e-5f);
        float* dst = g_W + b * WSTRIDE + woff + v * c;
        for (int cc = 0; cc < c; ++cc)
            dst[cc] = (row[cc] - mu) * inv * lnw[cc] + lnb[cc];
    }
}

// ---------------- K2: apply 4 hyper layers (f32x2 packed) --------------------
__global__ __launch_bounds__(256) void hyper_apply_kernel(
    const float* __restrict__ b0, const float* __restrict__ b1,
    const float* __restrict__ b2, const float* __restrict__ b3) {
    __shared__ float sW[WSTRIDE];
    __shared__ float sb[120];
    int b = blockIdx.y;
    int tid = threadIdx.x;
    const float* Wb = g_W + b * WSTRIDE;
    for (int i = tid; i < WSTRIDE; i += 256) sW[i] = Wb[i];
    if (tid < 30) sb[tid] = b0[tid];
    else if (tid < 60) sb[tid] = b1[tid - 30];
    else if (tid < 90) sb[tid] = b2[tid - 60];
    else if (tid < 120) sb[tid] = b3[tid - 90];
    __syncthreads();

    int p = blockIdx.x * 256 + tid;
    u64 hpr[31];
    const u64* e8 = (const u64*)(g_enc + p * 64);
#pragma unroll
    for (int i = 0; i < 31; ++i) hpr[i] = e8[i];

    float a[30];
#pragma unroll
    for (int oo = 0; oo < 30; ++oo) {
        const u64* w8 = (const u64*)(sW + oo * 62);
        u64 acc = 0ull;
#pragma unroll
        for (int i = 0; i < 31; ++i) acc = fma2(hpr[i], w8[i], acc);
        float2 f = up2(acc);
        a[oo] = silu_f(f.x + f.y + sb[oo]);
    }
#pragma unroll
    for (int l = 1; l <= 3; ++l) {
        int off = 1860 + (l - 1) * 900;
        u64 ap[15];
#pragma unroll
        for (int i = 0; i < 15; ++i) ap[i] = pk2(a[2 * i], a[2 * i + 1]);
        float t[30];
#pragma unroll
        for (int oo = 0; oo < 30; ++oo) {
            const u64* w8 = (const u64*)(sW + off + oo * 30);
            u64 acc = 0ull;
#pragma unroll
            for (int i = 0; i < 15; ++i) acc = fma2(ap[i], w8[i], acc);
            float2 f = up2(acc);
            t[oo] = silu_f(f.x + f.y + sb[l * 30 + oo]);
        }
#pragma unroll
        for (int oo = 0; oo < 30; ++oo) a[oo] = t[oo];
    }
    u64* gout = (u64*)(g_g + ((size_t)b * NPTS + p) * 30);
#pragma unroll
    for (int i = 0; i < 15; ++i) gout[i] = pk2(a[2 * i], a[2 * i + 1]);
}

// ---------------- K3: fused MLP as block GEMM --------------------------------
// Block: 256 threads, 64-point tile, loops over all 16 batches.
// smem layout (floats):
//   sW1  [256][132]  k-major W1, pitch 132         (offset 0,      33792 f)
//   sS   [256][68]   h1 activations, pitch 68      (offset 33792,  17408 f)
//   sGp  [15][64]    g pairs (u64)                 (offset 51200,   1920 f)
//   sRed [32][68]    partial reduction             (offset 53120,   2176 f)
//   sB1  [128]                                     (offset 55296)
//   sW2  [128]                                     (offset 55424)
#define K3_SMEM_FLOATS 55552
#define K3_SMEM_BYTES (K3_SMEM_FLOATS * 4)
#define TILE_P 64

__global__ __launch_bounds__(256, 1) void mlp_kernel(
    const float* __restrict__ w0, const float* __restrict__ b0,
    const float* __restrict__ w1, const float* __restrict__ b1,
    const float* __restrict__ w2, const float* __restrict__ b2v,
    float* __restrict__ out) {
    extern __shared__ float sm[];
    float* sW1  = sm;
    float* sS   = sm + 33792;
    u64*   sGp  = (u64*)(sm + 51200);
    float* sRed = sm + 53120;
    float* sB1  = sm + 55296;
    float* sW2  = sm + 55424;

    int tid = threadIdx.x;
    // stage W1 (coalesced gmem; 4-way STS conflict, once per block)
#pragma unroll 4
    for (int i = 0; i < 128; ++i)
        sW1[tid * 132 + i] = w1[i * 256 + tid];
    if (tid < 128) { sB1[tid] = b1[tid]; sW2[tid] = w2[tid]; }
    // W0 row for this thread's k, in registers
    float b0k = b0[tid];
    u64 w0r[15];
#pragma unroll
    for (int i = 0; i < 15; ++i)
        w0r[i] = *(const u64*)(w0 + tid * 30 + 2 * i);
    float bias2 = __ldg(b2v);

    int p0base = blockIdx.x * TILE_P;
    int tp = tid & 7, tj = tid >> 3;
    int j0 = tj * 4;

#pragma unroll 1
    for (int b = 0; b < NB; ++b) {
        // ---- load g tile (15 u64 x 64 points) ----
        for (int idx = tid; idx < 960; idx += 256) {
            int p = idx / 15, i = idx - p * 15;
            sGp[i * 64 + p] =
                *(const u64*)(g_g + ((size_t)b * NPTS + p0base + p) * 30 + 2 * i);
        }
        __syncthreads();

        // ---- phase 1: S[k=tid][p] = silu(W0 row . g[p] + b0[k]) ----
#pragma unroll 1
        for (int pb = 0; pb < 16; ++pb) {
            u64 a0 = 0ull, a1 = 0ull, a2 = 0ull, a3 = 0ull;
#pragma unroll
            for (int i = 0; i < 15; ++i) {
                const u64* gr = sGp + i * 64 + pb * 4;
                a0 = fma2(w0r[i], gr[0], a0);
                a1 = fma2(w0r[i], gr[1], a1);
                a2 = fma2(w0r[i], gr[2], a2);
                a3 = fma2(w0r[i], gr[3], a3);
            }
            float4 sv; float2 f;
            f = up2(a0); sv.x = silu_f(f.x + f.y + b0k);
            f = up2(a1); sv.y = silu_f(f.x + f.y + b0k);
            f = up2(a2); sv.z = silu_f(f.x + f.y + b0k);
            f = up2(a3); sv.w = silu_f(f.x + f.y + b0k);
            *(float4*)(sS + tid * 68 + pb * 4) = sv;
        }
        __syncthreads();

        // ---- GEMM: 4j x 8p register tile per thread ----
        u64 c[4][4];
#pragma unroll
        for (int jj = 0; jj < 4; ++jj) {
            float bv = sB1[j0 + jj];
            u64 bb = pk2(bv, bv);
            c[jj][0] = bb; c[jj][1] = bb; c[jj][2] = bb; c[jj][3] = bb;
        }
#pragma unroll 4
        for (int k = 0; k < 256; ++k) {
            float4 w = *(const float4*)(sW1 + k * 132 + j0);
            ulonglong2 sA = *(const ulonglong2*)(sS + k * 68 + tp * 4);
            ulonglong2 sBv = *(const ulonglong2*)(sS + k * 68 + 32 + tp * 4);
            u64 wp0 = pk2(w.x, w.x), wp1 = pk2(w.y, w.y);
            u64 wp2 = pk2(w.z, w.z), wp3 = pk2(w.w, w.w);
            c[0][0] = fma2(wp0, sA.x, c[0][0]); c[0][1] = fma2(wp0, sA.y, c[0][1]);
            c[0][2] = fma2(wp0, sBv.x, c[0][2]); c[0][3] = fma2(wp0, sBv.y, c[0][3]);
            c[1][0] = fma2(wp1, sA.x, c[1][0]); c[1][1] = fma2(wp1, sA.y, c[1][1]);
            c[1][2] = fma2(wp1, sBv.x, c[1][2]); c[1][3] = fma2(wp1, sBv.y, c[1][3]);
            c[2][0] = fma2(wp2, sA.x, c[2][0]); c[2][1] = fma2(wp2, sA.y, c[2][1]);
            c[2][2] = fma2(wp2, sBv.x, c[2][2]); c[2][3] = fma2(wp2, sBv.y, c[2][3]);
            c[3][0] = fma2(wp3, sA.x, c[3][0]); c[3][1] = fma2(wp3, sA.y, c[3][1]);
            c[3][2] = fma2(wp3, sBv.x, c[3][2]); c[3][3] = fma2(wp3, sBv.y, c[3][3]);
        }

        // ---- epilogue: silu + w2 dot, partials to sRed ----
        float r[8];
#pragma unroll
        for (int e = 0; e < 8; ++e) r[e] = 0.0f;
#pragma unroll
        for (int jj = 0; jj < 4; ++jj) {
            float wj = sW2[j0 + jj];
            float2 hA0 = up2(c[jj][0]), hA1 = up2(c[jj][1]);
            float2 hB0 = up2(c[jj][2]), hB1 = up2(c[jj][3]);
            r[0] = fmaf(wj, silu_f(hA0.x), r[0]);
            r[1] = fmaf(wj, silu_f(hA0.y), r[1]);
            r[2] = fmaf(wj, silu_f(hA1.x), r[2]);
            r[3] = fmaf(wj, silu_f(hA1.y), r[3]);
            r[4] = fmaf(wj, silu_f(hB0.x), r[4]);
            r[5] = fmaf(wj, silu_f(hB0.y), r[5]);
            r[6] = fmaf(wj, silu_f(hB1.x), r[6]);
            r[7] = fmaf(wj, silu_f(hB1.y), r[7]);
        }
        *(float4*)(sRed + tj * 68 + tp * 4) = make_float4(r[0], r[1], r[2], r[3]);
        *(float4*)(sRed + tj * 68 + 32 + tp * 4) = make_float4(r[4], r[5], r[6], r[7]);
        __syncthreads();

        if (tid < 64) {
            float s0 = 0.0f, s1 = 0.0f, s2 = 0.0f, s3 = 0.0f;
#pragma unroll
            for (int rr = 0; rr < 32; rr += 4) {
                s0 += sRed[rr * 68 + tid];
                s1 += sRed[(rr + 1) * 68 + tid];
                s2 += sRed[(rr + 2) * 68 + tid];
                s3 += sRed[(rr + 3) * 68 + tid];
            }
            out[(size_t)b * NPTS + p0base + tid] = s0 + s1 + s2 + s3 + bias2;
        }
        __syncthreads();
    }
}

// ---------------- launch -----------------------------------------------------
extern "C" void kernel_launch(void* const* d_in, const int* in_sizes, int n_in,
                              void* d_out, int out_size) {
    const float* x   = (const float*)d_in[0];
    const float* sdf = (const float*)d_in[1];
    HP hp;
    hp.pw[0]  = (const float*)d_in[2];  hp.pw[1]  = (const float*)d_in[7];
    hp.pw[2]  = (const float*)d_in[12]; hp.pw[3]  = (const float*)d_in[17];
    hp.pb[0]  = (const float*)d_in[3];  hp.pb[1]  = (const float*)d_in[8];
    hp.pb[2]  = (const float*)d_in[13]; hp.pb[3]  = (const float*)d_in[18];
    hp.lnw[0] = (const float*)d_in[4];  hp.lnw[1] = (const float*)d_in[9];
    hp.lnw[2] = (const float*)d_in[14]; hp.lnw[3] = (const float*)d_in[19];
    hp.lnb[0] = (const float*)d_in[5];  hp.lnb[1] = (const float*)d_in[10];
    hp.lnb[2] = (const float*)d_in[15]; hp.lnb[3] = (const float*)d_in[20];
    const float* bias[4] = {(const float*)d_in[6],  (const float*)d_in[11],
                            (const float*)d_in[16], (const float*)d_in[21]};
    const float* mw0 = (const float*)d_in[22];
    const float* mb0 = (const float*)d_in[23];
    const float* mw1 = (const float*)d_in[24];
    const float* mb1 = (const float*)d_in[25];
    const float* mw2 = (const float*)d_in[26];
    const float* mb2 = (const float*)d_in[27];
    float* out = (float*)d_out;

    cudaFuncSetAttribute(mlp_kernel, cudaFuncAttributeMaxDynamicSharedMemorySize,
                         K3_SMEM_BYTES);

    enc_kernel<<<NPTS / 256, 256>>>(x);
    hyperw_kernel<<<NB * 4, 256>>>(sdf, hp);

    dim3 g2(NPTS / 256, NB);
    hyper_apply_kernel<<<g2, 256>>>(bias[0], bias[1], bias[2], bias[3]);

    mlp_kernel<<<NPTS / TILE_P, 256, K3_SMEM_BYTES>>>(mw0, mb0, mw1, mb1, mw2, mb2, out);
}

// round 5
// speedup vs baseline: 2.2022x; 1.1427x over previous
#include <cuda_runtime.h>
#include <math.h>

#define NPTS 32768
#define NB 16
#define WSTRIDE 4560   // per-batch hyper weights: 30*62 + 3*30*30

typedef unsigned long long u64;

// ---------------- scratch (device globals; no allocations allowed) ----------
__device__ float g_W[NB * WSTRIDE];          // normalized hyper weights
__device__ float g_enc[NPTS * 64];           // nerf encoding, padded to 64
__device__ float g_g[NB * NPTS * 30];        // output of hyper layers (63MB)

// ---------------- packed f32x2 helpers (Blackwell) ---------------------------
__device__ __forceinline__ u64 pk2(float lo, float hi) {
    u64 r; asm("mov.b64 %0,{%1,%2};" : "=l"(r) : "f"(lo), "f"(hi)); return r;
}
__device__ __forceinline__ float2 up2(u64 v) {
    float2 r; asm("mov.b64 {%0,%1},%2;" : "=f"(r.x), "=f"(r.y) : "l"(v)); return r;
}
__device__ __forceinline__ u64 fma2(u64 a, u64 b, u64 c) {
    u64 r; asm("fma.rn.f32x2 %0,%1,%2,%3;" : "=l"(r) : "l"(a), "l"(b), "l"(c));
    return r;
}

// ---------------- misc helpers ----------------------------------------------
__device__ __forceinline__ float silu_f(float z) {
    float e = __expf(-z);
    return __fdividef(z, 1.0f + e);
}

// Pure-fp32 sin with 3-term Cody-Waite FMA reduction; accurate (~1e-7 abs)
// for |x| <= ~1e5 regardless of -use_fast_math. No FP64.
__device__ __forceinline__ float sin_cw(float x) {
    float kf = rintf(x * 0.63661977236758138f);
    float r = fmaf(kf, -1.57079637e+00f, x);   // pi/2 hi (0x3FC90FDB)
    r = fmaf(kf, 4.37113883e-08f, r);          // -mid
    r = fmaf(kf, 1.71512489e-15f, r);          // -lo
    int q = (int)kf;
    float s2 = r * r;
    float ps = fmaf(s2, 2.7525562e-6f, -1.9840874e-4f);
    ps = fmaf(s2, ps, 8.3333310e-3f);
    ps = fmaf(s2, ps, -1.6666667e-1f);
    float sinv = fmaf(r * s2, ps, r);
    float pc = fmaf(s2, 2.4433157e-5f, -1.3888378e-3f);
    pc = fmaf(s2, pc, 4.1666638e-2f);
    pc = fmaf(s2, pc, -0.5f);
    float cosv = fmaf(s2, pc, 1.0f);
    float res = (q & 1) ? cosv : sinv;
    if (q & 2) res = -res;
    return res;
}

// ---------------- K0: nerf encoding (all fp32) -------------------------------
__global__ __launch_bounds__(256) void enc_kernel(const float* __restrict__ x) {
    int p = blockIdx.x * 256 + threadIdx.x;
    float x0 = x[2 * p], x1 = x[2 * p + 1];
    float* o = g_enc + p * 64;
    const float HPI = 1.5707963267948966f;  // f32(pi/2): matches reference's f32 add
    o[0] = x0; o[1] = x1;
#pragma unroll
    for (int s = 0; s < 15; ++s) {
        float sc = (float)(1 << s);
        float a0 = x0 * sc, a1 = x1 * sc;
        o[2 + 2 * s]  = sin_cw(a0);
        o[3 + 2 * s]  = sin_cw(a1);
        o[32 + 2 * s] = sin_cw(a0 + HPI);
        o[33 + 2 * s] = sin_cw(a1 + HPI);
    }
    o[62] = 0.0f; o[63] = 0.0f;
}

// ---------------- K1: fused hyper weight generation (all 4 layers) ----------
struct HP {
    const float* pw[4];
    const float* pb[4];
    const float* lnw[4];
    const float* lnb[4];
};

__global__ __launch_bounds__(256) void hyperw_kernel(const float* __restrict__ sdf, HP hp) {
    __shared__ float wbuf[30 * 62];
    int b  = blockIdx.x & 15;
    int li = blockIdx.x >> 4;
    int c    = (li == 0) ? 62 : 30;
    int woff = (li == 0) ? 0  : 1860 + (li - 1) * 900;
    const float* pw  = hp.pw[li];
    const float* pb  = hp.pb[li];
    const float* lnw = hp.lnw[li];
    const float* lnb = hp.lnb[li];

    int tid = threadIdx.x;
    int tot = 30 * c;
    for (int e = tid; e < tot; e += 256) {
        int v = e / c, cc = e - v * c;
        const float4* sl4 = (const float4*)(sdf + ((b * 120) + li * 30 + v) * 120);
        const float4* pw4 = (const float4*)(pw + (v * c + cc) * 120);
        float acc = 0.0f;
#pragma unroll
        for (int d = 0; d < 30; ++d) {
            float4 a = sl4[d], w = pw4[d];
            acc = fmaf(a.x, w.x, acc); acc = fmaf(a.y, w.y, acc);
            acc = fmaf(a.z, w.z, acc); acc = fmaf(a.w, w.w, acc);
        }
        wbuf[e] = acc + pb[e];
    }
    __syncthreads();
    if (tid < 30) {
        int v = tid;
        const float* row = wbuf + v * c;
        float mu = 0.0f;
        for (int cc = 0; cc < c; ++cc) mu += row[cc];
        mu /= (float)c;
        float var = 0.0f;
        for (int cc = 0; cc < c; ++cc) { float d = row[cc] - mu; var = fmaf(d, d, var); }
        var /= (float)c;
        float inv = rsqrtf(var + 1e-5f);
        float* dst = g_W + b * WSTRIDE + woff + v * c;
        for (int cc = 0; cc < c; ++cc)
            dst[cc] = (row[cc] - mu) * inv * lnw[cc] + lnb[cc];
    }
}

// ---------------- K2: apply 4 hyper layers (f32x2 packed) --------------------
__global__ __launch_bounds__(256) void hyper_apply_kernel(
    const float* __restrict__ b0, const float* __restrict__ b1,
    const float* __restrict__ b2, const float* __restrict__ b3) {
    __shared__ float sW[WSTRIDE];
    __shared__ float sb[120];
    int b = blockIdx.y;
    int tid = threadIdx.x;
    const float* Wb = g_W + b * WSTRIDE;
    for (int i = tid; i < WSTRIDE; i += 256) sW[i] = Wb[i];
    if (tid < 30) sb[tid] = b0[tid];
    else if (tid < 60) sb[tid] = b1[tid - 30];
    else if (tid < 90) sb[tid] = b2[tid - 60];
    else if (tid < 120) sb[tid] = b3[tid - 90];
    __syncthreads();

    int p = blockIdx.x * 256 + tid;
    u64 hpr[31];
    const u64* e8 = (const u64*)(g_enc + p * 64);
#pragma unroll
    for (int i = 0; i < 31; ++i) hpr[i] = e8[i];

    float a[30];
#pragma unroll
    for (int oo = 0; oo < 30; ++oo) {
        const u64* w8 = (const u64*)(sW + oo * 62);
        u64 acc = 0ull;
#pragma unroll
        for (int i = 0; i < 31; ++i) acc = fma2(hpr[i], w8[i], acc);
        float2 f = up2(acc);
        a[oo] = silu_f(f.x + f.y + sb[oo]);
    }
#pragma unroll
    for (int l = 1; l <= 3; ++l) {
        int off = 1860 + (l - 1) * 900;
        u64 ap[15];
#pragma unroll
        for (int i = 0; i < 15; ++i) ap[i] = pk2(a[2 * i], a[2 * i + 1]);
        float t[30];
#pragma unroll
        for (int oo = 0; oo < 30; ++oo) {
            const u64* w8 = (const u64*)(sW + off + oo * 30);
            u64 acc = 0ull;
#pragma unroll
            for (int i = 0; i < 15; ++i) acc = fma2(ap[i], w8[i], acc);
            float2 f = up2(acc);
            t[oo] = silu_f(f.x + f.y + sb[l * 30 + oo]);
        }
#pragma unroll
        for (int oo = 0; oo < 30; ++oo) a[oo] = t[oo];
    }
    u64* gout = (u64*)(g_g + ((size_t)b * NPTS + p) * 30);
#pragma unroll
    for (int i = 0; i < 15; ++i) gout[i] = pk2(a[2 * i], a[2 * i + 1]);
}

// ---------------- K3: persistent fused MLP as block GEMM ---------------------
// grid=148 persistent blocks; each stages W1 once and loops over (p-tile, b)
// items. Per item: phase1 (k=tid row of 30->256), GEMM 128j x 64p with 4j x 8p
// register tiles, epilogue reduce.
#define K3_SMEM_FLOATS 55552
#define K3_SMEM_BYTES (K3_SMEM_FLOATS * 4)
#define TILE_P 64
#define MLP_BLOCKS 148
#define N_ITEMS ((NPTS / TILE_P) * NB)   // 8192

__global__ __launch_bounds__(256, 1) void mlp_kernel(
    const float* __restrict__ w0, const float* __restrict__ b0,
    const float* __restrict__ w1, const float* __restrict__ b1,
    const float* __restrict__ w2, const float* __restrict__ b2v,
    float* __restrict__ out) {
    extern __shared__ float sm[];
    float* sW1  = sm;                 // [256][132] k-major
    float* sS   = sm + 33792;         // [256][68]
    u64*   sGp  = (u64*)(sm + 51200); // [15][64]
    float* sRed = sm + 53120;         // [32][68]
    float* sB1  = sm + 55296;
    float* sW2  = sm + 55424;

    int tid = threadIdx.x;
#pragma unroll 4
    for (int i = 0; i < 128; ++i)
        sW1[tid * 132 + i] = w1[i * 256 + tid];
    if (tid < 128) { sB1[tid] = b1[tid]; sW2[tid] = w2[tid]; }
    float b0k = b0[tid];
    u64 w0r[15];
#pragma unroll
    for (int i = 0; i < 15; ++i)
        w0r[i] = *(const u64*)(w0 + tid * 30 + 2 * i);
    float bias2 = __ldg(b2v);

    int tp = tid & 7, tj = tid >> 3;
    int j0 = tj * 4;

#pragma unroll 1
    for (int item = blockIdx.x; item < N_ITEMS; item += MLP_BLOCKS) {
        int p0base = (item >> 4) * TILE_P;
        int b = item & 15;

        // ---- load g tile (15 u64 x 64 points) ----
        for (int idx = tid; idx < 960; idx += 256) {
            int p = idx / 15, i = idx - p * 15;
            sGp[i * 64 + p] =
                *(const u64*)(g_g + ((size_t)b * NPTS + p0base + p) * 30 + 2 * i);
        }
        __syncthreads();

        // ---- phase 1: S[k=tid][p] = silu(W0 row . g[p] + b0[k]) ----
#pragma unroll 1
        for (int pb = 0; pb < 16; ++pb) {
            u64 a0 = 0ull, a1 = 0ull, a2 = 0ull, a3 = 0ull;
#pragma unroll
            for (int i = 0; i < 15; ++i) {
                ulonglong2 g01 = *(const ulonglong2*)(sGp + i * 64 + pb * 4);
                ulonglong2 g23 = *(const ulonglong2*)(sGp + i * 64 + pb * 4 + 2);
                a0 = fma2(w0r[i], g01.x, a0);
                a1 = fma2(w0r[i], g01.y, a1);
                a2 = fma2(w0r[i], g23.x, a2);
                a3 = fma2(w0r[i], g23.y, a3);
            }
            float4 sv; float2 f;
            f = up2(a0); sv.x = silu_f(f.x + f.y + b0k);
            f = up2(a1); sv.y = silu_f(f.x + f.y + b0k);
            f = up2(a2); sv.z = silu_f(f.x + f.y + b0k);
            f = up2(a3); sv.w = silu_f(f.x + f.y + b0k);
            *(float4*)(sS + tid * 68 + pb * 4) = sv;
        }
        __syncthreads();

        // ---- GEMM: 4j x 8p register tile per thread ----
        u64 c[4][4];
#pragma unroll
        for (int jj = 0; jj < 4; ++jj) {
            float bv = sB1[j0 + jj];
            u64 bb = pk2(bv, bv);
            c[jj][0] = bb; c[jj][1] = bb; c[jj][2] = bb; c[jj][3] = bb;
        }
#pragma unroll 4
        for (int k = 0; k < 256; ++k) {
            float4 w = *(const float4*)(sW1 + k * 132 + j0);
            ulonglong2 sA = *(const ulonglong2*)(sS + k * 68 + tp * 4);
            ulonglong2 sBv = *(const ulonglong2*)(sS + k * 68 + 32 + tp * 4);
            u64 wp0 = pk2(w.x, w.x), wp1 = pk2(w.y, w.y);
            u64 wp2 = pk2(w.z, w.z), wp3 = pk2(w.w, w.w);
            c[0][0] = fma2(wp0, sA.x, c[0][0]); c[0][1] = fma2(wp0, sA.y, c[0][1]);
            c[0][2] = fma2(wp0, sBv.x, c[0][2]); c[0][3] = fma2(wp0, sBv.y, c[0][3]);
            c[1][0] = fma2(wp1, sA.x, c[1][0]); c[1][1] = fma2(wp1, sA.y, c[1][1]);
            c[1][2] = fma2(wp1, sBv.x, c[1][2]); c[1][3] = fma2(wp1, sBv.y, c[1][3]);
            c[2][0] = fma2(wp2, sA.x, c[2][0]); c[2][1] = fma2(wp2, sA.y, c[2][1]);
            c[2][2] = fma2(wp2, sBv.x, c[2][2]); c[2][3] = fma2(wp2, sBv.y, c[2][3]);
            c[3][0] = fma2(wp3, sA.x, c[3][0]); c[3][1] = fma2(wp3, sA.y, c[3][1]);
            c[3][2] = fma2(wp3, sBv.x, c[3][2]); c[3][3] = fma2(wp3, sBv.y, c[3][3]);
        }

        // ---- epilogue: silu + w2 dot, partials to sRed ----
        float r[8];
#pragma unroll
        for (int e = 0; e < 8; ++e) r[e] = 0.0f;
#pragma unroll
        for (int jj = 0; jj < 4; ++jj) {
            float wj = sW2[j0 + jj];
            float2 hA0 = up2(c[jj][0]), hA1 = up2(c[jj][1]);
            float2 hB0 = up2(c[jj][2]), hB1 = up2(c[jj][3]);
            r[0] = fmaf(wj, silu_f(hA0.x), r[0]);
            r[1] = fmaf(wj, silu_f(hA0.y), r[1]);
            r[2] = fmaf(wj, silu_f(hA1.x), r[2]);
            r[3] = fmaf(wj, silu_f(hA1.y), r[3]);
            r[4] = fmaf(wj, silu_f(hB0.x), r[4]);
            r[5] = fmaf(wj, silu_f(hB0.y), r[5]);
            r[6] = fmaf(wj, silu_f(hB1.x), r[6]);
            r[7] = fmaf(wj, silu_f(hB1.y), r[7]);
        }
        *(float4*)(sRed + tj * 68 + tp * 4) = make_float4(r[0], r[1], r[2], r[3]);
        *(float4*)(sRed + tj * 68 + 32 + tp * 4) = make_float4(r[4], r[5], r[6], r[7]);
        __syncthreads();

        if (tid < 64) {
            float s0 = 0.0f, s1 = 0.0f, s2 = 0.0f, s3 = 0.0f;
#pragma unroll
            for (int rr = 0; rr < 32; rr += 4) {
                s0 += sRed[rr * 68 + tid];
                s1 += sRed[(rr + 1) * 68 + tid];
                s2 += sRed[(rr + 2) * 68 + tid];
                s3 += sRed[(rr + 3) * 68 + tid];
            }
            out[(size_t)b * NPTS + p0base + tid] = s0 + s1 + s2 + s3 + bias2;
        }
        __syncthreads();
    }
}

// ---------------- launch -----------------------------------------------------
extern "C" void kernel_launch(void* const* d_in, const int* in_sizes, int n_in,
                              void* d_out, int out_size) {
    const float* x   = (const float*)d_in[0];
    const float* sdf = (const float*)d_in[1];
    HP hp;
    hp.pw[0]  = (const float*)d_in[2];  hp.pw[1]  = (const float*)d_in[7];
    hp.pw[2]  = (const float*)d_in[12]; hp.pw[3]  = (const float*)d_in[17];
    hp.pb[0]  = (const float*)d_in[3];  hp.pb[1]  = (const float*)d_in[8];
    hp.pb[2]  = (const float*)d_in[13]; hp.pb[3]  = (const float*)d_in[18];
    hp.lnw[0] = (const float*)d_in[4];  hp.lnw[1] = (const float*)d_in[9];
    hp.lnw[2] = (const float*)d_in[14]; hp.lnw[3] = (const float*)d_in[19];
    hp.lnb[0] = (const float*)d_in[5];  hp.lnb[1] = (const float*)d_in[10];
    hp.lnb[2] = (const float*)d_in[15]; hp.lnb[3] = (const float*)d_in[20];
    const float* bias[4] = {(const float*)d_in[6],  (const float*)d_in[11],
                            (const float*)d_in[16], (const float*)d_in[21]};
    const float* mw0 = (const float*)d_in[22];
    const float* mb0 = (const float*)d_in[23];
    const float* mw1 = (const float*)d_in[24];
    const float* mb1 = (const float*)d_in[25];
    const float* mw2 = (const float*)d_in[26];
    const float* mb2 = (const float*)d_in[27];
    float* out = (float*)d_out;

    cudaFuncSetAttribute(mlp_kernel, cudaFuncAttributeMaxDynamicSharedMemorySize,
                         K3_SMEM_BYTES);

    enc_kernel<<<NPTS / 256, 256>>>(x);
    hyperw_kernel<<<NB * 4, 256>>>(sdf, hp);

    dim3 g2(NPTS / 256, NB);
    hyper_apply_kernel<<<g2, 256>>>(bias[0], bias[1], bias[2], bias[3]);

    mlp_kernel<<<MLP_BLOCKS, 256, K3_SMEM_BYTES>>>(mw0, mb0, mw1, mb1, mw2, mb2, out);
}